// round 15
// baseline (speedup 1.0000x reference)
#include <cuda_runtime.h>
#include <math.h>
#include <stdint.h>

#define N_REGIONS 10
#define HIDDEN    128
#define HEADS     4
#define N_LAYERS  3
#define CHPR      7
#define TOKENS    16384
#define TW        6                          // tokens per CTA, M = 64 rows
#define NCTAS     ((TOKENS + TW - 1) / TW)   // 2731
#define NT        512                        // 16 warps: quads split N

typedef unsigned long long u64;
typedef uint32_t u32;

__constant__ int c_nbr_cnt[N_REGIONS] = {5,5,5,3,3,4,3,4,2,2};
__constant__ int c_nbr[N_REGIONS][5] = {
    {0,1,2,3,4},{0,1,2,5,7},{0,1,2,3,7},{0,2,3,0,0},{0,4,5,0,0},
    {1,4,5,6,0},{5,6,9,0,0},{1,2,7,8,0},{7,8,0,0,0},{6,9,0,0,0}
};
__constant__ float c_att_src[N_LAYERS * HEADS * HIDDEN];
__constant__ float c_att_dst[N_LAYERS * HEADS * HIDDEN];

// fragment-major packed W (tf32): idx = ((l*4+h)*256 + kt*16 + nt)*32 + lane
__device__ u64 g_Wpack[N_LAYERS * HEADS * 16 * 16 * 32];

__device__ __forceinline__ float gelu_exact(float v) {
    return 0.5f * v * (1.0f + erff(v * 0.70710678118654752f));
}
__device__ __forceinline__ u32 cvt_tf32(float f) {
    u32 r; asm("cvt.rna.tf32.f32 %0, %1;" : "=r"(r) : "f"(f)); return r;
}
// column permutation for nodesT: within each 8-col group, (tq, tq+4) pairs adjacent
__device__ __forceinline__ int permc(int e) {
    const int j = e & 7;
    return (e & ~7) + ((j & 3) << 1) + (j >> 2);
}
__device__ __forceinline__ void mma_tf32(float c[4], const u32 a[4], u32 b0, u32 b1) {
    asm volatile(
        "mma.sync.aligned.m16n8k8.row.col.f32.tf32.tf32.f32 "
        "{%0,%1,%2,%3}, {%4,%5,%6,%7}, {%8,%9}, {%0,%1,%2,%3};"
        : "+f"(c[0]), "+f"(c[1]), "+f"(c[2]), "+f"(c[3])
        : "r"(a[0]), "r"(a[1]), "r"(a[2]), "r"(a[3]), "r"(b0), "r"(b1));
}

__global__ void wpack_kernel(const float* __restrict__ W) {
    const int idx  = blockIdx.x * 256 + threadIdx.x;   // 98304 total
    const int lane = idx & 31;
    const int nt   = (idx >> 5) & 15;
    const int kt   = (idx >> 9) & 15;
    const int h    = (idx >> 13) & 3;
    const int l    = idx >> 15;
    const int tq = lane & 3, g = lane >> 2;
    const int k0 = kt * 8 + tq;
    const int e  = nt * 8 + g;
    const u32 b0 = cvt_tf32(W[((size_t)(l * 128 + k0)     * 4 + h) * 128 + e]);
    const u32 b1 = cvt_tf32(W[((size_t)(l * 128 + k0 + 4) * 4 + h) * 128 + e]);
    g_Wpack[idx] = ((u64)b1 << 32) | (u64)b0;
}

struct __align__(16) Smem {
    float nodes[64][132];        // fp32 residual stream; rows 60..63 zero pad
    u32   nodesT[64][132];       // tf32 shadow, PERMUTED columns (MMA1 A source)
    u32   hhT[64][132];          // per-head GEMM result, tf32 bits (MMA2 B source)
    u32   alphaT[6][10][10];     // alpha for current head, tf32 bits
    float aatt[4][64][8];        // dot partials per n-quarter
    float xs[TW * 70];
    float mu[64], rstd[64];
};

__global__ void __launch_bounds__(NT, 2) brain_mma_kernel(
    const float* __restrict__ x,
    const float* __restrict__ W_enc,
    const float* __restrict__ b_enc,
    const float* __restrict__ g_enc,
    const float* __restrict__ beta_enc,
    const float* __restrict__ b_gat,
    float* __restrict__ out)
{
    extern __shared__ Smem S[];
    const int t = threadIdx.x, w = t >> 5, lane = t & 31;
    const int g = lane >> 2, tq = lane & 3;
    const int wm = w & 3;                // strip index (shared by 4 warps)
    const int wh = w >> 2;               // n-quarter: ntiles [4wh, 4wh+4)
    const int tok0 = blockIdx.x * TW;
    const int r0 = wm * 16 + g;
    const int r8 = r0 + 8;
    const int e  = t & 127;              // feature col for elementwise phases
    const int th = t >> 7;               // 0..3

    // ---- zero pad rows, load inputs ----
    for (int i = t; i < 4 * 132; i += NT) {
        S->nodes [60 + i / 132][i % 132] = 0.0f;
        S->nodesT[60 + i / 132][i % 132] = 0u;
    }
    for (int i = t; i < TW * 70; i += NT) {
        const int tt = i / 70, tok = tok0 + tt;
        S->xs[i] = (tok < TOKENS) ? x[(size_t)tok * 70 + (i - tt * 70)] : 0.0f;
    }
    __syncthreads();

    // ---- encoder Linear(7,128): thread (th,e), tokens th, th+4 ----
    #pragma unroll 1
    for (int r = 0; r < N_REGIONS; r++) {
        float wv[CHPR];
        #pragma unroll
        for (int c = 0; c < CHPR; c++) wv[c] = W_enc[(r * CHPR + c) * 128 + e];
        const float bb = b_enc[r * 128 + e];
        #pragma unroll
        for (int q = 0; q < 2; q++) {
            const int tt = th + 4 * q;
            if (tt < TW) {
                float acc = bb;
                #pragma unroll
                for (int c = 0; c < CHPR; c++) acc += S->xs[tt * 70 + r * CHPR + c] * wv[c];
                S->nodes[tt * 10 + r][e] = acc;
            }
        }
    }
    __syncthreads();

    // ---- LayerNorm stats: rows 0..59 over 16 warps ----
    for (int row = w; row < 60; row += 16) {
        float v0 = S->nodes[row][lane];
        float v1 = S->nodes[row][lane + 32];
        float v2 = S->nodes[row][lane + 64];
        float v3 = S->nodes[row][lane + 96];
        float s  = v0 + v1 + v2 + v3;
        float sq = v0*v0 + v1*v1 + v2*v2 + v3*v3;
        #pragma unroll
        for (int o = 16; o > 0; o >>= 1) {
            s  += __shfl_xor_sync(0xffffffffu, s, o);
            sq += __shfl_xor_sync(0xffffffffu, sq, o);
        }
        if (lane == 0) {
            const float m = s * (1.0f / 128.0f);
            S->mu[row]   = m;
            S->rstd[row] = rsqrtf(sq * (1.0f / 128.0f) - m * m + 1e-5f);
        }
    }
    __syncthreads();

    // ---- LN affine + GELU -> nodes (+permuted tf32 shadow) + enc output ----
    {
        const int ep = permc(e);
        #pragma unroll 1
        for (int r = 0; r < N_REGIONS; r++) {
            const float ge = g_enc[r * 128 + e], be = beta_enc[r * 128 + e];
            #pragma unroll
            for (int q = 0; q < 2; q++) {
                const int tt = th + 4 * q;
                if (tt < TW) {
                    const int row = tt * 10 + r;
                    float v = (S->nodes[row][e] - S->mu[row]) * S->rstd[row] * ge + be;
                    const float gv = gelu_exact(v);
                    S->nodes [row][e]  = gv;
                    S->nodesT[row][ep] = cvt_tf32(gv);
                    if (tok0 + tt < TOKENS)
                        out[(size_t)TOKENS * 1280 + (size_t)(tok0 + tt) * 1280 + r * 128 + e] = gv;
                }
            }
        }
    }
    __syncthreads();

    // row->token mapping
    const int tokr  = r0 / 10, ir  = r0 - 10 * tokr;
    const int tokr8 = r8 / 10, ir8 = r8 - 10 * tokr8;
    const int vr  = (r0 < 60) ? tokr  : -1;
    const int vr8 = (r8 < 60) ? tokr8 : -1;

    // ---- GAT layers ----
    #pragma unroll 1
    for (int l = 0; l < N_LAYERS; l++) {
        float c2[4][4];
        #pragma unroll
        for (int nt = 0; nt < 4; nt++)
            #pragma unroll
            for (int ii = 0; ii < 4; ii++) c2[nt][ii] = 0.0f;

        #pragma unroll 1
        for (int h = 0; h < HEADS; h++) {
            // ===== MMA1: this warp's 4 n-tiles of hh = nodes @ W_{l,h} =====
            float asl = 0.0f, adl = 0.0f, ash = 0.0f, adh = 0.0f;
            {
                const u64* __restrict__ bph =
                    g_Wpack + (size_t)((l * 4 + h) * 256 + wh * 4) * 32 + lane;
                float c1[4][4];
                #pragma unroll
                for (int nt = 0; nt < 4; nt++)
                    #pragma unroll
                    for (int ii = 0; ii < 4; ii++) c1[nt][ii] = 0.0f;

                u64 bw[4];
                #pragma unroll
                for (int nt = 0; nt < 4; nt++) bw[nt] = __ldg(bph + nt * 32);

                #pragma unroll 1
                for (int kt = 0; kt < 16; kt++) {
                    const uint2 lo = *reinterpret_cast<const uint2*>(&S->nodesT[r0][kt * 8 + 2 * tq]);
                    const uint2 hi = *reinterpret_cast<const uint2*>(&S->nodesT[r8][kt * 8 + 2 * tq]);
                    u32 a[4];
                    a[0] = lo.x; a[1] = hi.x; a[2] = lo.y; a[3] = hi.y;
                    u64 bn[4];
                    const int nkt = (kt < 15) ? kt + 1 : 15;
                    #pragma unroll
                    for (int nt = 0; nt < 4; nt++)
                        bn[nt] = __ldg(bph + (nkt * 16 + nt) * 32);
                    #pragma unroll
                    for (int nt = 0; nt < 4; nt++)
                        mma_tf32(c1[nt], a, (u32)bw[nt], (u32)(bw[nt] >> 32));
                    #pragma unroll
                    for (int nt = 0; nt < 4; nt++) bw[nt] = bn[nt];
                }
                // store hh (tf32 bits) + dot partials
                #pragma unroll
                for (int nt = 0; nt < 4; nt++) {
                    const int col0 = (wh * 4 + nt) * 8 + 2 * tq;
                    uint2 p0, p8;
                    p0.x = cvt_tf32(c1[nt][0]); p0.y = cvt_tf32(c1[nt][1]);
                    p8.x = cvt_tf32(c1[nt][2]); p8.y = cvt_tf32(c1[nt][3]);
                    *reinterpret_cast<uint2*>(&S->hhT[r0][col0]) = p0;
                    *reinterpret_cast<uint2*>(&S->hhT[r8][col0]) = p8;
                    const float s0 = c_att_src[(l * 4 + h) * 128 + col0];
                    const float s1 = c_att_src[(l * 4 + h) * 128 + col0 + 1];
                    const float d0 = c_att_dst[(l * 4 + h) * 128 + col0];
                    const float d1 = c_att_dst[(l * 4 + h) * 128 + col0 + 1];
                    asl += c1[nt][0] * s0 + c1[nt][1] * s1;
                    adl += c1[nt][0] * d0 + c1[nt][1] * d1;
                    ash += c1[nt][2] * s0 + c1[nt][3] * s1;
                    adh += c1[nt][2] * d0 + c1[nt][3] * d1;
                }
            }
            // quad reduce, store per-quarter partials
            asl += __shfl_xor_sync(0xffffffffu, asl, 1); asl += __shfl_xor_sync(0xffffffffu, asl, 2);
            adl += __shfl_xor_sync(0xffffffffu, adl, 1); adl += __shfl_xor_sync(0xffffffffu, adl, 2);
            ash += __shfl_xor_sync(0xffffffffu, ash, 1); ash += __shfl_xor_sync(0xffffffffu, ash, 2);
            adh += __shfl_xor_sync(0xffffffffu, adh, 1); adh += __shfl_xor_sync(0xffffffffu, adh, 2);
            if (tq == 0) {
                *reinterpret_cast<float2*>(&S->aatt[wh][r0][2 * h]) = make_float2(asl, adl);
                *reinterpret_cast<float2*>(&S->aatt[wh][r8][2 * h]) = make_float2(ash, adh);
            }
            __syncthreads();

            // ===== softmax for head h (sum 4 n-quarter partials) =====
            if (t < 60) {
                const int tok = t / 10, i = t - 10 * tok;
                const float ad = S->aatt[0][t][2 * h + 1] + S->aatt[1][t][2 * h + 1]
                               + S->aatt[2][t][2 * h + 1] + S->aatt[3][t][2 * h + 1];
                u32 row10[10];
                #pragma unroll
                for (int j = 0; j < 10; j++) row10[j] = 0u;
                const int cnt = c_nbr_cnt[i];
                float lg[5];
                float mx = -1e30f;
                for (int q = 0; q < cnt; q++) {
                    const int jr = tok * 10 + c_nbr[i][q];
                    float v = ad + S->aatt[0][jr][2 * h] + S->aatt[1][jr][2 * h]
                                 + S->aatt[2][jr][2 * h] + S->aatt[3][jr][2 * h];
                    v = (v >= 0.0f) ? v : 0.2f * v;
                    lg[q] = v;
                    mx = fmaxf(mx, v);
                }
                float sum = 0.0f;
                for (int q = 0; q < cnt; q++) { lg[q] = expf(lg[q] - mx); sum += lg[q]; }
                const float inv = 1.0f / sum;
                for (int q = 0; q < cnt; q++) row10[c_nbr[i][q]] = cvt_tf32(lg[q] * inv);
                #pragma unroll
                for (int j = 0; j < 10; j++) S->alphaT[tok][i][j] = row10[j];
            }
            __syncthreads();

            // ===== MMA2: c2 += alpha_h (block-diag) @ hh_h, this warp's n-quarter =====
            #pragma unroll 1
            for (int kt = 0; kt < 8; kt++) {
                const int k1 = kt * 8 + tq, k2 = k1 + 4;
                const int tc1 = k1 / 10, j1 = k1 - 10 * tc1;
                const int tc2 = k2 / 10, j2 = k2 - 10 * tc2;
                u32 a[4];
                a[0] = (vr  == tc1) ? S->alphaT[tc1][ir ][j1] : 0u;
                a[1] = (vr8 == tc1) ? S->alphaT[tc1][ir8][j1] : 0u;
                a[2] = (vr  == tc2) ? S->alphaT[tc2][ir ][j2] : 0u;
                a[3] = (vr8 == tc2) ? S->alphaT[tc2][ir8][j2] : 0u;
                #pragma unroll
                for (int nt = 0; nt < 4; nt++) {
                    const int nc = (wh * 4 + nt) * 8 + g;
                    const u32 b0 = S->hhT[kt * 8 + tq][nc];
                    const u32 b1 = S->hhT[kt * 8 + tq + 4][nc];
                    mma_tf32(c2[nt], a, b0, b1);
                }
            }
            __syncthreads();   // hhT/alphaT free for next head
        } // heads

        // ===== epilogue: mean heads + bias + GELU + residual (+ permuted shadow) =====
        {
            const float* __restrict__ bgp = b_gat + l * 128;
            #pragma unroll
            for (int nt = 0; nt < 4; nt++) {
                const int col0 = (wh * 4 + nt) * 8 + 2 * tq;
                const int p0c = permc(col0), p1c = permc(col0 + 1);
                const float b0 = __ldg(bgp + col0), b1 = __ldg(bgp + col0 + 1);
                if (r0 < 60) {
                    const float n0 = gelu_exact(c2[nt][0] * 0.25f + b0) + S->nodes[r0][col0];
                    const float n1 = gelu_exact(c2[nt][1] * 0.25f + b1) + S->nodes[r0][col0 + 1];
                    *reinterpret_cast<float2*>(&S->nodes[r0][col0]) = make_float2(n0, n1);
                    S->nodesT[r0][p0c] = cvt_tf32(n0);
                    S->nodesT[r0][p1c] = cvt_tf32(n1);
                    if (l == N_LAYERS - 1 && tok0 + tokr < TOKENS)
                        *reinterpret_cast<float2*>(&out[(size_t)(tok0 + tokr) * 1280 + ir * 128 + col0])
                            = make_float2(n0, n1);
                }
                if (r8 < 60) {
                    const float n2 = gelu_exact(c2[nt][2] * 0.25f + b0) + S->nodes[r8][col0];
                    const float n3 = gelu_exact(c2[nt][3] * 0.25f + b1) + S->nodes[r8][col0 + 1];
                    *reinterpret_cast<float2*>(&S->nodes[r8][col0]) = make_float2(n2, n3);
                    S->nodesT[r8][p0c] = cvt_tf32(n2);
                    S->nodesT[r8][p1c] = cvt_tf32(n3);
                    if (l == N_LAYERS - 1 && tok0 + tokr8 < TOKENS)
                        *reinterpret_cast<float2*>(&out[(size_t)(tok0 + tokr8) * 1280 + ir8 * 128 + col0])
                            = make_float2(n2, n3);
                }
            }
        }
        __syncthreads();
    } // layers
}

extern "C" void kernel_launch(void* const* d_in, const int* in_sizes, int n_in,
                              void* d_out, int out_size) {
    (void)in_sizes; (void)n_in; (void)out_size;
    const float* x        = (const float*)d_in[0];
    const float* W_enc    = (const float*)d_in[1];
    const float* b_enc    = (const float*)d_in[2];
    const float* g_enc    = (const float*)d_in[3];
    const float* beta_enc = (const float*)d_in[4];
    const float* W_gat    = (const float*)d_in[5];
    const float* att_src  = (const float*)d_in[6];
    const float* att_dst  = (const float*)d_in[7];
    const float* b_gat    = (const float*)d_in[8];
    float* out = (float*)d_out;

    static_assert(sizeof(Smem) <= 112 * 1024, "smem too big for 2 CTAs/SM");
    cudaFuncSetAttribute(brain_mma_kernel,
                         cudaFuncAttributeMaxDynamicSharedMemorySize, (int)sizeof(Smem));

    cudaMemcpyToSymbolAsync(c_att_src, att_src, N_LAYERS * HEADS * HIDDEN * sizeof(float),
                            0, cudaMemcpyDeviceToDevice);
    cudaMemcpyToSymbolAsync(c_att_dst, att_dst, N_LAYERS * HEADS * HIDDEN * sizeof(float),
                            0, cudaMemcpyDeviceToDevice);
    wpack_kernel<<<(N_LAYERS * HEADS * 16 * 16 * 32) / 256, 256>>>(W_gat);
    brain_mma_kernel<<<NCTAS, NT, sizeof(Smem)>>>(
        x, W_enc, b_enc, g_enc, beta_enc, b_gat, out);
}

// round 16
// speedup vs baseline: 1.2205x; 1.2205x over previous
#include <cuda_runtime.h>
#include <math.h>
#include <stdint.h>

#define N_REGIONS 10
#define HIDDEN    128
#define HEADS     4
#define N_LAYERS  3
#define CHPR      7
#define TOKENS    16384
#define TW        6                          // tokens per CTA, M = 64 rows
#define NCTAS     ((TOKENS + TW - 1) / TW)   // 2731
#define NT        256                        // 8 warps: pairs split N (R13 shape)

typedef unsigned long long u64;
typedef uint32_t u32;

__constant__ int c_nbr_cnt[N_REGIONS] = {5,5,5,3,3,4,3,4,2,2};
__constant__ int c_nbr[N_REGIONS][5] = {
    {0,1,2,3,4},{0,1,2,5,7},{0,1,2,3,7},{0,2,3,0,0},{0,4,5,0,0},
    {1,4,5,6,0},{5,6,9,0,0},{1,2,7,8,0},{7,8,0,0,0},{6,9,0,0,0}
};
__constant__ float c_att_src[N_LAYERS * HEADS * HIDDEN];
__constant__ float c_att_dst[N_LAYERS * HEADS * HIDDEN];

// fragment-major packed W (tf32): idx = ((l*4+h)*256 + kt*16 + nt)*32 + lane
__device__ u64 g_Wpack[N_LAYERS * HEADS * 16 * 16 * 32];

__device__ __forceinline__ float gelu_exact(float v) {
    return 0.5f * v * (1.0f + erff(v * 0.70710678118654752f));
}
__device__ __forceinline__ u32 cvt_tf32(float f) {
    u32 r; asm("cvt.rna.tf32.f32 %0, %1;" : "=r"(r) : "f"(f)); return r;
}
// column permutation: within each 8-col group, (tq, tq+4) pairs adjacent
__device__ __forceinline__ int permc(int e) {
    const int j = e & 7;
    return (e & ~7) + ((j & 3) << 1) + (j >> 2);
}
__device__ __forceinline__ void mma_tf32(float c[4], const u32 a[4], u32 b0, u32 b1) {
    asm volatile(
        "mma.sync.aligned.m16n8k8.row.col.f32.tf32.tf32.f32 "
        "{%0,%1,%2,%3}, {%4,%5,%6,%7}, {%8,%9}, {%0,%1,%2,%3};"
        : "+f"(c[0]), "+f"(c[1]), "+f"(c[2]), "+f"(c[3])
        : "r"(a[0]), "r"(a[1]), "r"(a[2]), "r"(a[3]), "r"(b0), "r"(b1));
}

__global__ void wpack_kernel(const float* __restrict__ W) {
    const int idx  = blockIdx.x * 256 + threadIdx.x;   // 98304 total
    const int lane = idx & 31;
    const int nt   = (idx >> 5) & 15;
    const int kt   = (idx >> 9) & 15;
    const int h    = (idx >> 13) & 3;
    const int l    = idx >> 15;
    const int tq = lane & 3, g = lane >> 2;
    const int k0 = kt * 8 + tq;
    const int e  = nt * 8 + g;
    const u32 b0 = cvt_tf32(W[((size_t)(l * 128 + k0)     * 4 + h) * 128 + e]);
    const u32 b1 = cvt_tf32(W[((size_t)(l * 128 + k0 + 4) * 4 + h) * 128 + e]);
    g_Wpack[idx] = ((u64)b1 << 32) | (u64)b0;
}

struct __align__(16) Smem {
    u32   nodesT[64][132];   // tf32 shadow, PERMUTED cols (MMA1 A); fp32 scratch in prologue via hhT
    u32   hhT[64][132];      // per-head hh tf32 bits (MMA2 B); fp32 scratch in prologue
    u32   alphaRow[64][68];  // block-diagonal alpha (60x60 live), PERMUTED cols, zero background
    float aatt[2][64][8];    // dot partials per n-half
    float xs[TW * 70];
    float mu[64], rstd[64];
};

__global__ void __launch_bounds__(NT, 2) brain_mma_kernel(
    const float* __restrict__ x,
    const float* __restrict__ W_enc,
    const float* __restrict__ b_enc,
    const float* __restrict__ g_enc,
    const float* __restrict__ beta_enc,
    const float* __restrict__ b_gat,
    float* __restrict__ out)
{
    extern __shared__ Smem S[];
    const int t = threadIdx.x, w = t >> 5, lane = t & 31;
    const int g = lane >> 2, tq = lane & 3;
    const int wm = w & 3;                // strip index (shared by warp pair)
    const int wh = w >> 2;               // n-half: ntiles [8wh, 8wh+8)
    const int tok0 = blockIdx.x * TW;
    const int r0 = wm * 16 + g;
    const int r8 = r0 + 8;
    const int e  = t & 127;
    const int th = t >> 7;

    float* scratch = (float*)S->hhT;     // fp32 view during prologue

    // ---- zero alphaRow (background stays zero forever) + nodesT pad rows; load x ----
    for (int i = t; i < 64 * 68; i += NT) S->alphaRow[i / 68][i % 68] = 0u;
    for (int i = t; i < 4 * 132; i += NT) S->nodesT[60 + i / 132][i % 132] = 0u;
    for (int i = t; i < TW * 70; i += NT) {
        const int tt = i / 70, tok = tok0 + tt;
        S->xs[i] = (tok < TOKENS) ? x[(size_t)tok * 70 + (i - tt * 70)] : 0.0f;
    }
    __syncthreads();

    // ---- encoder Linear(7,128) -> scratch ----
    #pragma unroll 1
    for (int r = 0; r < N_REGIONS; r++) {
        float wv[CHPR];
        #pragma unroll
        for (int c = 0; c < CHPR; c++) wv[c] = W_enc[(r * CHPR + c) * 128 + e];
        const float bb = b_enc[r * 128 + e];
        #pragma unroll
        for (int q = 0; q < 3; q++) {
            const int tt = th + 2 * q;
            float acc = bb;
            #pragma unroll
            for (int c = 0; c < CHPR; c++) acc += S->xs[tt * 70 + r * CHPR + c] * wv[c];
            scratch[(tt * 10 + r) * 132 + e] = acc;
        }
    }
    __syncthreads();

    // ---- LayerNorm stats ----
    for (int row = w; row < 60; row += 8) {
        float v0 = scratch[row * 132 + lane];
        float v1 = scratch[row * 132 + lane + 32];
        float v2 = scratch[row * 132 + lane + 64];
        float v3 = scratch[row * 132 + lane + 96];
        float s  = v0 + v1 + v2 + v3;
        float sq = v0*v0 + v1*v1 + v2*v2 + v3*v3;
        #pragma unroll
        for (int o = 16; o > 0; o >>= 1) {
            s  += __shfl_xor_sync(0xffffffffu, s, o);
            sq += __shfl_xor_sync(0xffffffffu, sq, o);
        }
        if (lane == 0) {
            const float m = s * (1.0f / 128.0f);
            S->mu[row]   = m;
            S->rstd[row] = rsqrtf(sq * (1.0f / 128.0f) - m * m + 1e-5f);
        }
    }
    __syncthreads();

    // ---- LN affine + GELU -> nodesT (permuted) + enc output (also layer-0 residual) ----
    {
        const int ep = permc(e);
        #pragma unroll 1
        for (int r = 0; r < N_REGIONS; r++) {
            const float ge = g_enc[r * 128 + e], be = beta_enc[r * 128 + e];
            #pragma unroll
            for (int q = 0; q < 3; q++) {
                const int tt = th + 2 * q;
                const int row = tt * 10 + r;
                float v = (scratch[row * 132 + e] - S->mu[row]) * S->rstd[row] * ge + be;
                const float gv = gelu_exact(v);
                S->nodesT[row][ep] = cvt_tf32(gv);
                if (tok0 + tt < TOKENS)
                    out[(size_t)TOKENS * 1280 + (size_t)(tok0 + tt) * 1280 + r * 128 + e] = gv;
            }
        }
    }
    __syncthreads();

    // row->token mapping
    const int tokr  = r0 / 10, ir  = r0 - 10 * tokr;
    const int tokr8 = r8 / 10, ir8 = r8 - 10 * tokr8;
    const bool okr  = (r0 < 60) && (tok0 + tokr  < TOKENS);
    const bool okr8 = (r8 < 60) && (tok0 + tokr8 < TOKENS);

    // ---- GAT layers ----
    #pragma unroll 1
    for (int l = 0; l < N_LAYERS; l++) {
        float c2[8][4];
        #pragma unroll
        for (int nt = 0; nt < 8; nt++)
            #pragma unroll
            for (int ii = 0; ii < 4; ii++) c2[nt][ii] = 0.0f;

        #pragma unroll 1
        for (int h = 0; h < HEADS; h++) {
            // ===== MMA1: this warp's 8 n-tiles of hh = nodes @ W_{l,h} =====
            float asl = 0.0f, adl = 0.0f, ash = 0.0f, adh = 0.0f;
            {
                const u64* __restrict__ bph =
                    g_Wpack + (size_t)((l * 4 + h) * 256 + wh * 8) * 32 + lane;
                float c1[8][4];
                #pragma unroll
                for (int nt = 0; nt < 8; nt++)
                    #pragma unroll
                    for (int ii = 0; ii < 4; ii++) c1[nt][ii] = 0.0f;

                u64 bw[8];
                #pragma unroll
                for (int nt = 0; nt < 8; nt++) bw[nt] = __ldg(bph + nt * 32);

                #pragma unroll 1
                for (int kt = 0; kt < 16; kt++) {
                    const uint2 lo = *reinterpret_cast<const uint2*>(&S->nodesT[r0][kt * 8 + 2 * tq]);
                    const uint2 hi = *reinterpret_cast<const uint2*>(&S->nodesT[r8][kt * 8 + 2 * tq]);
                    u32 a[4];
                    a[0] = lo.x; a[1] = hi.x; a[2] = lo.y; a[3] = hi.y;
                    u64 bn[8];
                    const int nkt = (kt < 15) ? kt + 1 : 15;
                    #pragma unroll
                    for (int nt = 0; nt < 8; nt++)
                        bn[nt] = __ldg(bph + (nkt * 16 + nt) * 32);
                    #pragma unroll
                    for (int nt = 0; nt < 8; nt++)
                        mma_tf32(c1[nt], a, (u32)bw[nt], (u32)(bw[nt] >> 32));
                    #pragma unroll
                    for (int nt = 0; nt < 8; nt++) bw[nt] = bn[nt];
                }
                // store hh (tf32 bits) + dot partials
                #pragma unroll
                for (int nt = 0; nt < 8; nt++) {
                    const int col0 = (wh * 8 + nt) * 8 + 2 * tq;
                    uint2 p0, p8;
                    p0.x = cvt_tf32(c1[nt][0]); p0.y = cvt_tf32(c1[nt][1]);
                    p8.x = cvt_tf32(c1[nt][2]); p8.y = cvt_tf32(c1[nt][3]);
                    *reinterpret_cast<uint2*>(&S->hhT[r0][col0]) = p0;
                    *reinterpret_cast<uint2*>(&S->hhT[r8][col0]) = p8;
                    const float s0 = c_att_src[(l * 4 + h) * 128 + col0];
                    const float s1 = c_att_src[(l * 4 + h) * 128 + col0 + 1];
                    const float d0 = c_att_dst[(l * 4 + h) * 128 + col0];
                    const float d1 = c_att_dst[(l * 4 + h) * 128 + col0 + 1];
                    asl += c1[nt][0] * s0 + c1[nt][1] * s1;
                    adl += c1[nt][0] * d0 + c1[nt][1] * d1;
                    ash += c1[nt][2] * s0 + c1[nt][3] * s1;
                    adh += c1[nt][2] * d0 + c1[nt][3] * d1;
                }
            }
            // quad reduce, store per-half partials
            asl += __shfl_xor_sync(0xffffffffu, asl, 1); asl += __shfl_xor_sync(0xffffffffu, asl, 2);
            adl += __shfl_xor_sync(0xffffffffu, adl, 1); adl += __shfl_xor_sync(0xffffffffu, adl, 2);
            ash += __shfl_xor_sync(0xffffffffu, ash, 1); ash += __shfl_xor_sync(0xffffffffu, ash, 2);
            adh += __shfl_xor_sync(0xffffffffu, adh, 1); adh += __shfl_xor_sync(0xffffffffu, adh, 2);
            if (tq == 0) {
                *reinterpret_cast<float2*>(&S->aatt[wh][r0][2 * h]) = make_float2(asl, adl);
                *reinterpret_cast<float2*>(&S->aatt[wh][r8][2 * h]) = make_float2(ash, adh);
            }
            __syncthreads();

            // ===== softmax for head h -> block-diagonal alphaRow (permuted cols) =====
            if (t < 60) {
                const int tok = t / 10, i = t - 10 * tok;
                const float ad = S->aatt[0][t][2 * h + 1] + S->aatt[1][t][2 * h + 1];
                const int cnt = c_nbr_cnt[i];
                float lg[5];
                float mx = -1e30f;
                for (int q = 0; q < cnt; q++) {
                    const int jr = tok * 10 + c_nbr[i][q];
                    float v = ad + S->aatt[0][jr][2 * h] + S->aatt[1][jr][2 * h];
                    v = (v >= 0.0f) ? v : 0.2f * v;
                    lg[q] = v;
                    mx = fmaxf(mx, v);
                }
                float sum = 0.0f;
                for (int q = 0; q < cnt; q++) { lg[q] = __expf(lg[q] - mx); sum += lg[q]; }
                const float inv = 1.0f / sum;
                for (int q = 0; q < cnt; q++)
                    S->alphaRow[t][permc(tok * 10 + c_nbr[i][q])] = cvt_tf32(lg[q] * inv);
            }
            __syncthreads();

            // ===== MMA2: c2 += alphaRow (block-diag) @ hh_h, this warp's n-half =====
            #pragma unroll
            for (int kt = 0; kt < 8; kt++) {
                const uint2 alo = *reinterpret_cast<const uint2*>(&S->alphaRow[r0][kt * 8 + 2 * tq]);
                const uint2 ahi = *reinterpret_cast<const uint2*>(&S->alphaRow[r8][kt * 8 + 2 * tq]);
                u32 a[4];
                a[0] = alo.x; a[1] = ahi.x; a[2] = alo.y; a[3] = ahi.y;
                #pragma unroll
                for (int nt = 0; nt < 8; nt++) {
                    const int nc = (wh * 8 + nt) * 8 + g;
                    const u32 b0 = S->hhT[kt * 8 + tq][nc];
                    const u32 b1 = S->hhT[kt * 8 + tq + 4][nc];
                    mma_tf32(c2[nt], a, b0, b1);
                }
            }
            __syncthreads();   // hhT/alphaRow free for next head
        } // heads

        // ===== epilogue: mean + bias + GELU + residual(gmem) -> gf + nodesT =====
        {
            const float* __restrict__ bgp = b_gat + l * 128;
            const size_t resoff = (l == 0) ? (size_t)TOKENS * 1280 : 0;
            #pragma unroll
            for (int nt = 0; nt < 8; nt++) {
                const int col0 = (wh * 8 + nt) * 8 + 2 * tq;
                const int p0c = permc(col0), p1c = permc(col0 + 1);
                const float b0 = __ldg(bgp + col0), b1 = __ldg(bgp + col0 + 1);
                if (okr) {
                    const size_t gfo = (size_t)(tok0 + tokr) * 1280 + ir * 128 + col0;
                    const float2 res = *reinterpret_cast<const float2*>(&out[resoff + gfo]);
                    const float n0 = gelu_exact(c2[nt][0] * 0.25f + b0) + res.x;
                    const float n1 = gelu_exact(c2[nt][1] * 0.25f + b1) + res.y;
                    *reinterpret_cast<float2*>(&out[gfo]) = make_float2(n0, n1);
                    S->nodesT[r0][p0c] = cvt_tf32(n0);
                    S->nodesT[r0][p1c] = cvt_tf32(n1);
                }
                if (okr8) {
                    const size_t gfo = (size_t)(tok0 + tokr8) * 1280 + ir8 * 128 + col0;
                    const float2 res = *reinterpret_cast<const float2*>(&out[resoff + gfo]);
                    const float n2 = gelu_exact(c2[nt][2] * 0.25f + b0) + res.x;
                    const float n3 = gelu_exact(c2[nt][3] * 0.25f + b1) + res.y;
                    *reinterpret_cast<float2*>(&out[gfo]) = make_float2(n2, n3);
                    S->nodesT[r8][p0c] = cvt_tf32(n2);
                    S->nodesT[r8][p1c] = cvt_tf32(n3);
                }
            }
        }
        __syncthreads();
    } // layers
}

extern "C" void kernel_launch(void* const* d_in, const int* in_sizes, int n_in,
                              void* d_out, int out_size) {
    (void)in_sizes; (void)n_in; (void)out_size;
    const float* x        = (const float*)d_in[0];
    const float* W_enc    = (const float*)d_in[1];
    const float* b_enc    = (const float*)d_in[2];
    const float* g_enc    = (const float*)d_in[3];
    const float* beta_enc = (const float*)d_in[4];
    const float* W_gat    = (const float*)d_in[5];
    const float* att_src  = (const float*)d_in[6];
    const float* att_dst  = (const float*)d_in[7];
    const float* b_gat    = (const float*)d_in[8];
    float* out = (float*)d_out;

    static_assert(sizeof(Smem) <= 95 * 1024, "smem too big for 2 CTAs/SM");
    cudaFuncSetAttribute(brain_mma_kernel,
                         cudaFuncAttributeMaxDynamicSharedMemorySize, (int)sizeof(Smem));

    cudaMemcpyToSymbolAsync(c_att_src, att_src, N_LAYERS * HEADS * HIDDEN * sizeof(float),
                            0, cudaMemcpyDeviceToDevice);
    cudaMemcpyToSymbolAsync(c_att_dst, att_dst, N_LAYERS * HEADS * HIDDEN * sizeof(float),
                            0, cudaMemcpyDeviceToDevice);
    wpack_kernel<<<(N_LAYERS * HEADS * 16 * 16 * 32) / 256, 256>>>(W_gat);
    brain_mma_kernel<<<NCTAS, NT, sizeof(Smem)>>>(
        x, W_enc, b_enc, g_enc, beta_enc, b_gat, out);
}

// round 17
// speedup vs baseline: 1.2782x; 1.0473x over previous
#include <cuda_runtime.h>
#include <math.h>
#include <stdint.h>

#define N_REGIONS 10
#define HIDDEN    128
#define HEADS     4
#define N_LAYERS  3
#define CHPR      7
#define TOKENS    16384
#define TW        6                          // tokens per CTA, M = 64 rows
#define NCTAS     ((TOKENS + TW - 1) / TW)   // 2731
#define NT        256                        // 8 warps: pairs split N

typedef unsigned long long u64;
typedef uint32_t u32;

__constant__ int c_nbr_cnt[N_REGIONS] = {5,5,5,3,3,4,3,4,2,2};
__constant__ int c_nbr[N_REGIONS][5] = {
    {0,1,2,3,4},{0,1,2,5,7},{0,1,2,3,7},{0,2,3,0,0},{0,4,5,0,0},
    {1,4,5,6,0},{5,6,9,0,0},{1,2,7,8,0},{7,8,0,0,0},{6,9,0,0,0}
};
__constant__ float c_att_src[N_LAYERS * HEADS * HIDDEN];
__constant__ float c_att_dst[N_LAYERS * HEADS * HIDDEN];

// uint4-packed fragment-major W (tf32 bits): slot = (((l*4+h)*16 + kt)*8 + p)*32 + lane
// .x = b0(nt=2p), .y = b1(nt=2p), .z = b0(nt=2p+1), .w = b1(nt=2p+1)
__device__ uint4 g_Wpk[N_LAYERS * HEADS * 16 * 8 * 32];

__device__ __forceinline__ float gelu_exact(float v) {
    return 0.5f * v * (1.0f + erff(v * 0.70710678118654752f));
}
__device__ __forceinline__ u32 cvt_tf32(float f) {
    u32 r; asm("cvt.rna.tf32.f32 %0, %1;" : "=r"(r) : "f"(f)); return r;
}
// permutation: within each 8-idx group, (tq, tq+4) pairs adjacent
__device__ __forceinline__ int permc(int e) {
    const int j = e & 7;
    return (e & ~7) + ((j & 3) << 1) + (j >> 2);
}
__device__ __forceinline__ void mma_tf32(float c[4], const u32 a[4], u32 b0, u32 b1) {
    asm volatile(
        "mma.sync.aligned.m16n8k8.row.col.f32.tf32.tf32.f32 "
        "{%0,%1,%2,%3}, {%4,%5,%6,%7}, {%8,%9}, {%0,%1,%2,%3};"
        : "+f"(c[0]), "+f"(c[1]), "+f"(c[2]), "+f"(c[3])
        : "r"(a[0]), "r"(a[1]), "r"(a[2]), "r"(a[3]), "r"(b0), "r"(b1));
}

__global__ void wpack_kernel(const float* __restrict__ W) {
    const int idx  = blockIdx.x * 256 + threadIdx.x;   // 49152 total
    const int lane = idx & 31;
    const int p    = (idx >> 5) & 7;
    const int kt   = (idx >> 8) & 15;
    const int h    = (idx >> 12) & 3;
    const int l    = idx >> 14;
    const int tq = lane & 3, g = lane >> 2;
    const int k0 = kt * 8 + tq;
    const int e0 = (2 * p) * 8 + g;
    const int e1 = e0 + 8;
    uint4 v;
    v.x = cvt_tf32(W[((size_t)(l * 128 + k0)     * 4 + h) * 128 + e0]);
    v.y = cvt_tf32(W[((size_t)(l * 128 + k0 + 4) * 4 + h) * 128 + e0]);
    v.z = cvt_tf32(W[((size_t)(l * 128 + k0)     * 4 + h) * 128 + e1]);
    v.w = cvt_tf32(W[((size_t)(l * 128 + k0 + 4) * 4 + h) * 128 + e1]);
    g_Wpk[idx] = v;
}

struct __align__(16) Smem {
    u32   nodesT[64][132];   // tf32 shadow, PERMUTED cols (MMA1 A source)
    u32   hhTt[128][68];     // TRANSPOSED hh, tf32 bits: [n][permuted k] (MMA2 B source)
    u32   alphaRow[64][68];  // block-diag alpha, PERMUTED cols, zero background
    float aatt[2][64][8];    // dot partials per n-half
    float xs[TW * 70];
    float mu[64], rstd[64];
};

__global__ void __launch_bounds__(NT, 2) brain_mma_kernel(
    const float* __restrict__ x,
    const float* __restrict__ W_enc,
    const float* __restrict__ b_enc,
    const float* __restrict__ g_enc,
    const float* __restrict__ beta_enc,
    const float* __restrict__ b_gat,
    float* __restrict__ out)
{
    extern __shared__ Smem S[];
    const int t = threadIdx.x, w = t >> 5, lane = t & 31;
    const int g = lane >> 2, tq = lane & 3;
    const int wm = w & 3;                // strip index (shared by warp pair)
    const int wh = w >> 2;               // n-half: ntiles [8wh, 8wh+8)
    const int tok0 = blockIdx.x * TW;
    const int r0 = wm * 16 + g;
    const int r8 = r0 + 8;
    const int e  = t & 127;
    const int th = t >> 7;

    float* scratch = (float*)S->hhTt;    // fp32 view during prologue (8448 <= 8704 slots)

    // ---- zero alphaRow + nodesT pad rows; load x ----
    for (int i = t; i < 64 * 68; i += NT) S->alphaRow[i / 68][i % 68] = 0u;
    for (int i = t; i < 4 * 132; i += NT) S->nodesT[60 + i / 132][i % 132] = 0u;
    for (int i = t; i < TW * 70; i += NT) {
        const int tt = i / 70, tok = tok0 + tt;
        S->xs[i] = (tok < TOKENS) ? x[(size_t)tok * 70 + (i - tt * 70)] : 0.0f;
    }
    __syncthreads();

    // ---- encoder Linear(7,128) -> scratch ----
    #pragma unroll 1
    for (int r = 0; r < N_REGIONS; r++) {
        float wv[CHPR];
        #pragma unroll
        for (int c = 0; c < CHPR; c++) wv[c] = W_enc[(r * CHPR + c) * 128 + e];
        const float bb = b_enc[r * 128 + e];
        #pragma unroll
        for (int q = 0; q < 3; q++) {
            const int tt = th + 2 * q;
            float acc = bb;
            #pragma unroll
            for (int c = 0; c < CHPR; c++) acc += S->xs[tt * 70 + r * CHPR + c] * wv[c];
            scratch[(tt * 10 + r) * 132 + e] = acc;
        }
    }
    __syncthreads();

    // ---- LayerNorm stats ----
    for (int row = w; row < 60; row += 8) {
        float v0 = scratch[row * 132 + lane];
        float v1 = scratch[row * 132 + lane + 32];
        float v2 = scratch[row * 132 + lane + 64];
        float v3 = scratch[row * 132 + lane + 96];
        float s  = v0 + v1 + v2 + v3;
        float sq = v0*v0 + v1*v1 + v2*v2 + v3*v3;
        #pragma unroll
        for (int o = 16; o > 0; o >>= 1) {
            s  += __shfl_xor_sync(0xffffffffu, s, o);
            sq += __shfl_xor_sync(0xffffffffu, sq, o);
        }
        if (lane == 0) {
            const float m = s * (1.0f / 128.0f);
            S->mu[row]   = m;
            S->rstd[row] = rsqrtf(sq * (1.0f / 128.0f) - m * m + 1e-5f);
        }
    }
    __syncthreads();

    // ---- LN affine + GELU -> nodesT (permuted) + enc output ----
    {
        const int ep = permc(e);
        #pragma unroll 1
        for (int r = 0; r < N_REGIONS; r++) {
            const float ge = g_enc[r * 128 + e], be = beta_enc[r * 128 + e];
            #pragma unroll
            for (int q = 0; q < 3; q++) {
                const int tt = th + 2 * q;
                const int row = tt * 10 + r;
                float v = (scratch[row * 132 + e] - S->mu[row]) * S->rstd[row] * ge + be;
                const float gv = gelu_exact(v);
                S->nodesT[row][ep] = cvt_tf32(gv);
                if (tok0 + tt < TOKENS)
                    out[(size_t)TOKENS * 1280 + (size_t)(tok0 + tt) * 1280 + r * 128 + e] = gv;
            }
        }
    }
    __syncthreads();

    // row->token mapping
    const int tokr  = r0 / 10, ir  = r0 - 10 * tokr;
    const int tokr8 = r8 / 10, ir8 = r8 - 10 * tokr8;
    const bool okr  = (r0 < 60) && (tok0 + tokr  < TOKENS);
    const bool okr8 = (r8 < 60) && (tok0 + tokr8 < TOKENS);
    const int pkr0 = permc(r0), pkr8 = permc(r8);

    // ---- GAT layers ----
    #pragma unroll 1
    for (int l = 0; l < N_LAYERS; l++) {
        float c2[8][4];
        #pragma unroll
        for (int nt = 0; nt < 8; nt++)
            #pragma unroll
            for (int ii = 0; ii < 4; ii++) c2[nt][ii] = 0.0f;

        #pragma unroll 1
        for (int h = 0; h < HEADS; h++) {
            // ===== MMA1: this warp's 8 n-tiles of hh = nodes @ W_{l,h} =====
            float asl = 0.0f, adl = 0.0f, ash = 0.0f, adh = 0.0f;
            {
                const uint4* __restrict__ bph =
                    g_Wpk + (size_t)((l * 4 + h) * 128) * 32 + lane;
                float c1[8][4];
                #pragma unroll
                for (int nt = 0; nt < 8; nt++)
                    #pragma unroll
                    for (int ii = 0; ii < 4; ii++) c1[nt][ii] = 0.0f;

                #pragma unroll 4
                for (int kt = 0; kt < 16; kt++) {
                    uint4 wq[4];
                    #pragma unroll
                    for (int j = 0; j < 4; j++)
                        wq[j] = __ldg(bph + (size_t)(kt * 8 + wh * 4 + j) * 32);
                    const uint2 lo = *reinterpret_cast<const uint2*>(&S->nodesT[r0][kt * 8 + 2 * tq]);
                    const uint2 hi = *reinterpret_cast<const uint2*>(&S->nodesT[r8][kt * 8 + 2 * tq]);
                    u32 a[4];
                    a[0] = lo.x; a[1] = hi.x; a[2] = lo.y; a[3] = hi.y;
                    #pragma unroll
                    for (int j = 0; j < 4; j++) {
                        mma_tf32(c1[2 * j],     a, wq[j].x, wq[j].y);
                        mma_tf32(c1[2 * j + 1], a, wq[j].z, wq[j].w);
                    }
                }
                // store hh transposed (tf32 bits) + dot partials
                #pragma unroll
                for (int nt = 0; nt < 8; nt++) {
                    const int col0 = (wh * 8 + nt) * 8 + 2 * tq;
                    S->hhTt[col0]    [pkr0] = cvt_tf32(c1[nt][0]);
                    S->hhTt[col0 + 1][pkr0] = cvt_tf32(c1[nt][1]);
                    S->hhTt[col0]    [pkr8] = cvt_tf32(c1[nt][2]);
                    S->hhTt[col0 + 1][pkr8] = cvt_tf32(c1[nt][3]);
                    const float s0 = c_att_src[(l * 4 + h) * 128 + col0];
                    const float s1 = c_att_src[(l * 4 + h) * 128 + col0 + 1];
                    const float d0 = c_att_dst[(l * 4 + h) * 128 + col0];
                    const float d1 = c_att_dst[(l * 4 + h) * 128 + col0 + 1];
                    asl += c1[nt][0] * s0 + c1[nt][1] * s1;
                    adl += c1[nt][0] * d0 + c1[nt][1] * d1;
                    ash += c1[nt][2] * s0 + c1[nt][3] * s1;
                    adh += c1[nt][2] * d0 + c1[nt][3] * d1;
                }
            }
            // quad reduce, store per-half partials
            asl += __shfl_xor_sync(0xffffffffu, asl, 1); asl += __shfl_xor_sync(0xffffffffu, asl, 2);
            adl += __shfl_xor_sync(0xffffffffu, adl, 1); adl += __shfl_xor_sync(0xffffffffu, adl, 2);
            ash += __shfl_xor_sync(0xffffffffu, ash, 1); ash += __shfl_xor_sync(0xffffffffu, ash, 2);
            adh += __shfl_xor_sync(0xffffffffu, adh, 1); adh += __shfl_xor_sync(0xffffffffu, adh, 2);
            if (tq == 0) {
                *reinterpret_cast<float2*>(&S->aatt[wh][r0][2 * h]) = make_float2(asl, adl);
                *reinterpret_cast<float2*>(&S->aatt[wh][r8][2 * h]) = make_float2(ash, adh);
            }
            __syncthreads();

            // ===== softmax for head h -> block-diagonal alphaRow (permuted cols) =====
            if (t < 60) {
                const int tok = t / 10, i = t - 10 * tok;
                const float ad = S->aatt[0][t][2 * h + 1] + S->aatt[1][t][2 * h + 1];
                const int cnt = c_nbr_cnt[i];
                float lg[5];
                float mx = -1e30f;
                for (int q = 0; q < cnt; q++) {
                    const int jr = tok * 10 + c_nbr[i][q];
                    float v = ad + S->aatt[0][jr][2 * h] + S->aatt[1][jr][2 * h];
                    v = (v >= 0.0f) ? v : 0.2f * v;
                    lg[q] = v;
                    mx = fmaxf(mx, v);
                }
                float sum = 0.0f;
                for (int q = 0; q < cnt; q++) { lg[q] = __expf(lg[q] - mx); sum += lg[q]; }
                const float inv = 1.0f / sum;
                for (int q = 0; q < cnt; q++)
                    S->alphaRow[t][permc(tok * 10 + c_nbr[i][q])] = cvt_tf32(lg[q] * inv);
            }
            __syncthreads();

            // ===== MMA2: c2 += alphaRow (block-diag) @ hh_h, this warp's n-half =====
            #pragma unroll
            for (int kt = 0; kt < 8; kt++) {
                const uint2 alo = *reinterpret_cast<const uint2*>(&S->alphaRow[r0][kt * 8 + 2 * tq]);
                const uint2 ahi = *reinterpret_cast<const uint2*>(&S->alphaRow[r8][kt * 8 + 2 * tq]);
                u32 a[4];
                a[0] = alo.x; a[1] = ahi.x; a[2] = alo.y; a[3] = ahi.y;
                #pragma unroll
                for (int nt = 0; nt < 8; nt++) {
                    const uint2 b = *reinterpret_cast<const uint2*>(
                        &S->hhTt[(wh * 8 + nt) * 8 + g][kt * 8 + 2 * tq]);
                    mma_tf32(c2[nt], a, b.x, b.y);
                }
            }
            __syncthreads();   // hhTt/alphaRow free for next head
        } // heads

        // ===== epilogue: mean + bias + GELU + residual(gmem) -> gf + nodesT =====
        {
            const float* __restrict__ bgp = b_gat + l * 128;
            const size_t resoff = (l == 0) ? (size_t)TOKENS * 1280 : 0;
            #pragma unroll
            for (int nt = 0; nt < 8; nt++) {
                const int col0 = (wh * 8 + nt) * 8 + 2 * tq;
                const int p0c = permc(col0), p1c = permc(col0 + 1);
                const float b0 = __ldg(bgp + col0), b1 = __ldg(bgp + col0 + 1);
                if (okr) {
                    const size_t gfo = (size_t)(tok0 + tokr) * 1280 + ir * 128 + col0;
                    const float2 res = *reinterpret_cast<const float2*>(&out[resoff + gfo]);
                    const float n0 = gelu_exact(c2[nt][0] * 0.25f + b0) + res.x;
                    const float n1 = gelu_exact(c2[nt][1] * 0.25f + b1) + res.y;
                    *reinterpret_cast<float2*>(&out[gfo]) = make_float2(n0, n1);
                    S->nodesT[r0][p0c] = cvt_tf32(n0);
                    S->nodesT[r0][p1c] = cvt_tf32(n1);
                }
                if (okr8) {
                    const size_t gfo = (size_t)(tok0 + tokr8) * 1280 + ir8 * 128 + col0;
                    const float2 res = *reinterpret_cast<const float2*>(&out[resoff + gfo]);
                    const float n2 = gelu_exact(c2[nt][2] * 0.25f + b0) + res.x;
                    const float n3 = gelu_exact(c2[nt][3] * 0.25f + b1) + res.y;
                    *reinterpret_cast<float2*>(&out[gfo]) = make_float2(n2, n3);
                    S->nodesT[r8][p0c] = cvt_tf32(n2);
                    S->nodesT[r8][p1c] = cvt_tf32(n3);
                }
            }
        }
        __syncthreads();
    } // layers
}

extern "C" void kernel_launch(void* const* d_in, const int* in_sizes, int n_in,
                              void* d_out, int out_size) {
    (void)in_sizes; (void)n_in; (void)out_size;
    const float* x        = (const float*)d_in[0];
    const float* W_enc    = (const float*)d_in[1];
    const float* b_enc    = (const float*)d_in[2];
    const float* g_enc    = (const float*)d_in[3];
    const float* beta_enc = (const float*)d_in[4];
    const float* W_gat    = (const float*)d_in[5];
    const float* att_src  = (const float*)d_in[6];
    const float* att_dst  = (const float*)d_in[7];
    const float* b_gat    = (const float*)d_in[8];
    float* out = (float*)d_out;

    static_assert(sizeof(Smem) <= 96 * 1024, "smem too big for 2 CTAs/SM");
    cudaFuncSetAttribute(brain_mma_kernel,
                         cudaFuncAttributeMaxDynamicSharedMemorySize, (int)sizeof(Smem));

    cudaMemcpyToSymbolAsync(c_att_src, att_src, N_LAYERS * HEADS * HIDDEN * sizeof(float),
                            0, cudaMemcpyDeviceToDevice);
    cudaMemcpyToSymbolAsync(c_att_dst, att_dst, N_LAYERS * HEADS * HIDDEN * sizeof(float),
                            0, cudaMemcpyDeviceToDevice);
    wpack_kernel<<<(N_LAYERS * HEADS * 16 * 8 * 32) / 256, 256>>>(W_gat);
    brain_mma_kernel<<<NCTAS, NT, sizeof(Smem)>>>(
        x, W_enc, b_enc, g_enc, beta_enc, b_gat, out);
}